// round 8
// baseline (speedup 1.0000x reference)
#include <cuda_runtime.h>
#include <cuda_bf16.h>

#define NUM_USERS 100000
#define NUM_ITEMS 200000
#define NN        (NUM_USERS + NUM_ITEMS)   // 300000
#define D         64
#define NNZ       5000000
#define BATCH     16384
#define WIDTH     32                         // ELL width (P(deg>32) ~ 5e-5, spill net)
#define MAX_SPILL 2048

// Full layer outputs for layers 1,2 (each 76.8 MB); layer 3 fused into final.
__device__ float g_A[(size_t)NN * D];
__device__ float g_B[(size_t)NN * D];

// ELL storage: packed (col, val_bits). 300000*32*8B = 76.8 MB (L2-resident)
__device__ int2 g_ell[(size_t)NN * WIDTH];
__device__ int  g_len[NN];

// Spill safety net (degree > WIDTH; expected ~tens of edges)
__device__ int   g_spill_count;
__device__ int   g_srow[MAX_SPILL];
__device__ int   g_scol[MAX_SPILL];
__device__ float g_sval[MAX_SPILL];

// ---------------------------------------------------------------------------
__global__ void init_kernel() {
    int i = blockIdx.x * blockDim.x + threadIdx.x;
    const int n4 = NN / 4;                    // 75000
    if (i < n4)
        reinterpret_cast<int4*>(g_len)[i] = make_int4(0, 0, 0, 0);
    if (i == 0) g_spill_count = 0;
}

// 8 edges per thread: 8 independent atomics in flight, then 8 scattered stores.
__global__ void ell_fill_kernel(const int*   __restrict__ erow,
                                const int*   __restrict__ ecol,
                                const float* __restrict__ evals) {
    int t = blockIdx.x * blockDim.x + threadIdx.x;
    int i8 = t * 8;
    if (i8 >= NNZ) return;

    int4   r0 = *reinterpret_cast<const int4*>(erow + i8);
    int4   r1 = *reinterpret_cast<const int4*>(erow + i8 + 4);
    int4   c0 = *reinterpret_cast<const int4*>(ecol + i8);
    int4   c1 = *reinterpret_cast<const int4*>(ecol + i8 + 4);
    float4 v0 = *reinterpret_cast<const float4*>(evals + i8);
    float4 v1 = *reinterpret_cast<const float4*>(evals + i8 + 4);

    int   rows[8] = {r0.x, r0.y, r0.z, r0.w, r1.x, r1.y, r1.z, r1.w};
    int   cols[8] = {c0.x, c0.y, c0.z, c0.w, c1.x, c1.y, c1.z, c1.w};
    float vals[8] = {v0.x, v0.y, v0.z, v0.w, v1.x, v1.y, v1.z, v1.w};

    int pos[8];
#pragma unroll
    for (int k = 0; k < 8; k++)
        pos[k] = atomicAdd(&g_len[rows[k]], 1);   // 8 independent atomics
#pragma unroll
    for (int k = 0; k < 8; k++) {
        if (pos[k] < WIDTH) {
            g_ell[(size_t)rows[k] * WIDTH + pos[k]] =
                make_int2(cols[k], __float_as_int(vals[k]));
        } else {
            int s = atomicAdd(&g_spill_count, 1);
            if (s < MAX_SPILL) {
                g_srow[s] = rows[k]; g_scol[s] = cols[k]; g_sval[s] = vals[k];
            }
        }
    }
}

// ---------------------------------------------------------------------------
// Warp computes one output row. n_raw = full degree (may exceed WIDTH).
// Padding iterations carry c=0, v=0: load row 0 (L1-hot), FMA adds 0.
__device__ __forceinline__ float2 spmm_row_acc(int node, int n_raw, int lane,
                                               const float* __restrict__ su,
                                               const float* __restrict__ si) {
    int n = min(n_raw, WIDTH);
    int2 ev = make_int2(0, 0);
    if (lane < n)
        ev = __ldcs(g_ell + (size_t)node * WIDTH + lane);  // evict-first stream

    float2 acc = make_float2(0.f, 0.f);
    int n4 = (n + 3) & ~3;
    for (int j = 0; j < n4; j += 4) {
#pragma unroll
        for (int k = 0; k < 4; k++) {
            int   cj = __shfl_sync(0xFFFFFFFFu, ev.x, j + k);
            float vj = __int_as_float(__shfl_sync(0xFFFFFFFFu, ev.y, j + k));
            const float* srow = (cj < NUM_USERS)
                              ? (su + (size_t)cj * D)
                              : (si + (size_t)(cj - NUM_USERS) * D);
            float2 x = *reinterpret_cast<const float2*>(srow + 2 * lane);
            acc.x += vj * x.x;
            acc.y += vj * x.y;
        }
    }

    if (n_raw > WIDTH) {                       // rare: ~16 rows in the graph
        int cnt = min(g_spill_count, MAX_SPILL);
        for (int s = 0; s < cnt; s++) {
            if (g_srow[s] == node) {
                int   cj = g_scol[s];
                float vj = g_sval[s];
                const float* srow = (cj < NUM_USERS)
                                  ? (su + (size_t)cj * D)
                                  : (si + (size_t)(cj - NUM_USERS) * D);
                float2 x = *reinterpret_cast<const float2*>(srow + 2 * lane);
                acc.x += vj * x.x;
                acc.y += vj * x.y;
            }
        }
    }
    return acc;
}

// Full SpMM (layers 1, 2): one warp per destination row, streaming store.
// Spill handling is inline (no separate mop-up kernel).
__global__ void spmm_ell_kernel(const float* __restrict__ uemb,
                                const float* __restrict__ iemb,
                                int stage) {
    int warp = (blockIdx.x * blockDim.x + threadIdx.x) >> 5;
    int lane = threadIdx.x & 31;
    if (warp >= NN) return;

    const float* su; const float* si; float* dst;
    if (stage == 0) { su = uemb; si = iemb;                        dst = g_A; }
    else            { su = g_A;  si = g_A + (size_t)NUM_USERS * D; dst = g_B; }

    int n_raw = g_len[warp];
    float2 acc = spmm_row_acc(warp, n_raw, lane, su, si);
    __stcs(reinterpret_cast<float2*>(dst + (size_t)warp * D + 2 * lane), acc);
}

// ---------------------------------------------------------------------------
// Fused layer-3 + dot: one warp per pair; u and i gathers interleaved for ILP.
// gamma[b] = dot( (e0_u+e1_u+e2_u+e3_u)/4 , (e0_i+e1_i+e2_i+e3_i)/4 )
__global__ void final_kernel(const int*   __restrict__ users,
                             const int*   __restrict__ items,
                             const float* __restrict__ uemb,
                             const float* __restrict__ iemb,
                             float*       __restrict__ out) {
    int warp = (blockIdx.x * blockDim.x + threadIdx.x) >> 5;
    int lane = threadIdx.x & 31;
    if (warp >= BATCH) return;

    int u  = __ldg(users + warp);
    int it = __ldg(items + warp);
    int nu = u;
    int ni = NUM_USERS + it;

    const float* bu = g_B;
    const float* bi = g_B + (size_t)NUM_USERS * D;

    // --- fused layer-3 gathers for both endpoints, interleaved ---
    int nru = g_len[nu];
    int nri = g_len[ni];
    int n_u = min(nru, WIDTH);
    int n_i = min(nri, WIDTH);

    int2 evu = make_int2(0, 0), evi = make_int2(0, 0);
    if (lane < n_u) evu = __ldcs(g_ell + (size_t)nu * WIDTH + lane);
    if (lane < n_i) evi = __ldcs(g_ell + (size_t)ni * WIDTH + lane);

    float2 e3u = make_float2(0.f, 0.f);
    float2 e3i = make_float2(0.f, 0.f);
    int nmax = (max(n_u, n_i) + 3) & ~3;
    for (int j = 0; j < nmax; j += 4) {
#pragma unroll
        for (int k = 0; k < 4; k++) {
            int   cu = __shfl_sync(0xFFFFFFFFu, evu.x, j + k);
            float vu = __int_as_float(__shfl_sync(0xFFFFFFFFu, evu.y, j + k));
            int   ci = __shfl_sync(0xFFFFFFFFu, evi.x, j + k);
            float vi = __int_as_float(__shfl_sync(0xFFFFFFFFu, evi.y, j + k));
            if (j + k >= n_u) { cu = 0; vu = 0.f; }
            if (j + k >= n_i) { ci = 0; vi = 0.f; }
            const float* ru = (cu < NUM_USERS)
                            ? (bu + (size_t)cu * D)
                            : (bi + (size_t)(cu - NUM_USERS) * D);
            const float* ri = (ci < NUM_USERS)
                            ? (bu + (size_t)ci * D)
                            : (bi + (size_t)(ci - NUM_USERS) * D);
            float2 xu = *reinterpret_cast<const float2*>(ru + 2 * lane);
            float2 xi = *reinterpret_cast<const float2*>(ri + 2 * lane);
            e3u.x += vu * xu.x;  e3u.y += vu * xu.y;
            e3i.x += vi * xi.x;  e3i.y += vi * xi.y;
        }
    }
    // rare spill patch
    if (nru > WIDTH || nri > WIDTH) {
        int cnt = min(g_spill_count, MAX_SPILL);
        for (int s = 0; s < cnt; s++) {
            int   rs = g_srow[s];
            if (rs != nu && rs != ni) continue;
            int   cj = g_scol[s];
            float vj = g_sval[s];
            const float* sr = (cj < NUM_USERS)
                            ? (bu + (size_t)cj * D)
                            : (bi + (size_t)(cj - NUM_USERS) * D);
            float2 x = *reinterpret_cast<const float2*>(sr + 2 * lane);
            if (rs == nu) { e3u.x += vj * x.x; e3u.y += vj * x.y; }
            if (rs == ni) { e3i.x += vj * x.x; e3i.y += vj * x.y; }
        }
    }

    size_t urow = (size_t)nu * D + 2 * lane;
    size_t irow = (size_t)ni * D + 2 * lane;

    float2 a_u = *reinterpret_cast<const float2*>(g_A + urow);
    float2 b_u = *reinterpret_cast<const float2*>(g_B + urow);
    float2 e0u = *reinterpret_cast<const float2*>(uemb + (size_t)u * D + 2 * lane);
    float2 a_i = *reinterpret_cast<const float2*>(g_A + irow);
    float2 b_i = *reinterpret_cast<const float2*>(g_B + irow);
    float2 e0i = *reinterpret_cast<const float2*>(iemb + (size_t)it * D + 2 * lane);

    float uvx = e0u.x + a_u.x + b_u.x + e3u.x;
    float uvy = e0u.y + a_u.y + b_u.y + e3u.y;
    float ivx = e0i.x + a_i.x + b_i.x + e3i.x;
    float ivy = e0i.y + a_i.y + b_i.y + e3i.y;

    float dot = uvx * ivx + uvy * ivy;
#pragma unroll
    for (int off = 16; off > 0; off >>= 1)
        dot += __shfl_xor_sync(0xFFFFFFFFu, dot, off);

    if (lane == 0) out[warp] = dot * 0.0625f;   // (1/4)*(1/4)
}

// ---------------------------------------------------------------------------
extern "C" void kernel_launch(void* const* d_in, const int* in_sizes, int n_in,
                              void* d_out, int out_size) {
    const int*   users = (const int*)  d_in[0];
    const int*   items = (const int*)  d_in[1];
    const int*   erow  = (const int*)  d_in[2];
    const int*   ecol  = (const int*)  d_in[3];
    const float* evals = (const float*)d_in[4];
    const float* uemb  = (const float*)d_in[5];
    const float* iemb  = (const float*)d_in[6];
    float* out = (float*)d_out;

    // --- build ELL ---
    init_kernel<<<(NN / 4 + 255) / 256, 256>>>();
    ell_fill_kernel<<<(NNZ / 8 + 255) / 256, 256>>>(erow, ecol, evals);

    int threads = 256;                         // 8 warps/block
    int blocks  = (NN + 7) / 8;                // 37500

    // --- layers 1,2 full (spill inline); layer 3 fused into final ---
    spmm_ell_kernel<<<blocks, threads>>>(uemb, iemb, 0);
    spmm_ell_kernel<<<blocks, threads>>>(uemb, iemb, 1);

    // --- fused layer-3 + gather + dot ---
    final_kernel<<<(BATCH + 7) / 8, 256>>>(users, items, uemb, iemb, out);
}

// round 9
// speedup vs baseline: 1.1962x; 1.1962x over previous
#include <cuda_runtime.h>
#include <cuda_bf16.h>

#define NUM_USERS 100000
#define NUM_ITEMS 200000
#define NN        (NUM_USERS + NUM_ITEMS)   // 300000
#define D         64
#define NNZ       5000000
#define BATCH     16384
#define WIDTH     32                         // ELL width (P(deg>32) ~ 5e-5, spill net)
#define MAX_SPILL 2048

// Full layer outputs for layers 1,2 (each 76.8 MB); layer 3 fused into final.
__device__ float g_A[(size_t)NN * D];
__device__ float g_B[(size_t)NN * D];

// ELL storage: packed (col, val_bits). 300000*32*8B = 76.8 MB (L2-resident)
__device__ int2 g_ell[(size_t)NN * WIDTH];
__device__ int  g_len[NN];

// Spill safety net (degree > WIDTH; expected ~tens of edges)
__device__ int   g_spill_count;
__device__ int   g_srow[MAX_SPILL];
__device__ int   g_scol[MAX_SPILL];
__device__ float g_sval[MAX_SPILL];

// ---------------------------------------------------------------------------
__global__ void init_kernel() {
    int i = blockIdx.x * blockDim.x + threadIdx.x;
    const int n4 = NN / 4;                    // 75000
    if (i < n4)
        reinterpret_cast<int4*>(g_len)[i] = make_int4(0, 0, 0, 0);
    if (i == 0) g_spill_count = 0;
}

// 8 edges per thread: 8 independent atomics in flight, then 8 scattered stores.
__global__ void ell_fill_kernel(const int*   __restrict__ erow,
                                const int*   __restrict__ ecol,
                                const float* __restrict__ evals) {
    int t = blockIdx.x * blockDim.x + threadIdx.x;
    int i8 = t * 8;
    if (i8 >= NNZ) return;

    int4   r0 = *reinterpret_cast<const int4*>(erow + i8);
    int4   r1 = *reinterpret_cast<const int4*>(erow + i8 + 4);
    int4   c0 = *reinterpret_cast<const int4*>(ecol + i8);
    int4   c1 = *reinterpret_cast<const int4*>(ecol + i8 + 4);
    float4 v0 = *reinterpret_cast<const float4*>(evals + i8);
    float4 v1 = *reinterpret_cast<const float4*>(evals + i8 + 4);

    int   rows[8] = {r0.x, r0.y, r0.z, r0.w, r1.x, r1.y, r1.z, r1.w};
    int   cols[8] = {c0.x, c0.y, c0.z, c0.w, c1.x, c1.y, c1.z, c1.w};
    float vals[8] = {v0.x, v0.y, v0.z, v0.w, v1.x, v1.y, v1.z, v1.w};

    int pos[8];
#pragma unroll
    for (int k = 0; k < 8; k++)
        pos[k] = atomicAdd(&g_len[rows[k]], 1);   // 8 independent atomics
#pragma unroll
    for (int k = 0; k < 8; k++) {
        if (pos[k] < WIDTH) {
            g_ell[(size_t)rows[k] * WIDTH + pos[k]] =
                make_int2(cols[k], __float_as_int(vals[k]));
        } else {
            int s = atomicAdd(&g_spill_count, 1);
            if (s < MAX_SPILL) {
                g_srow[s] = rows[k]; g_scol[s] = cols[k]; g_sval[s] = vals[k];
            }
        }
    }
}

// ---------------------------------------------------------------------------
// stage 0: src = (uemb, iemb), dst = g_A ; stage 1: src = g_A, dst = g_B
__device__ __forceinline__ void stage_ptrs(int stage,
                                           const float* uemb, const float* iemb,
                                           const float*& su, const float*& si,
                                           float*& dst) {
    if (stage == 0) { su = uemb; si = iemb;                        dst = g_A; }
    else            { su = g_A;  si = g_A + (size_t)NUM_USERS * D; dst = g_B; }
}

// Warp computes one output row (single ELL chunk, len <= 32). LEAN: no spill
// logic in here — keeps register pressure low (round-8 lesson).
__device__ __forceinline__ float2 spmm_row_acc(int node, int lane,
                                               const float* __restrict__ su,
                                               const float* __restrict__ si) {
    int n = min(g_len[node], WIDTH);
    int2 ev = make_int2(0, 0);
    if (lane < n)
        ev = __ldcs(g_ell + (size_t)node * WIDTH + lane);  // evict-first stream

    float2 acc = make_float2(0.f, 0.f);
    int n4 = (n + 3) & ~3;
    for (int j = 0; j < n4; j += 4) {
#pragma unroll
        for (int k = 0; k < 4; k++) {
            int   cj = __shfl_sync(0xFFFFFFFFu, ev.x, j + k);
            float vj = __int_as_float(__shfl_sync(0xFFFFFFFFu, ev.y, j + k));
            const float* srow = (cj < NUM_USERS)
                              ? (su + (size_t)cj * D)
                              : (si + (size_t)(cj - NUM_USERS) * D);
            float2 x = *reinterpret_cast<const float2*>(srow + 2 * lane);
            acc.x += vj * x.x;
            acc.y += vj * x.y;
        }
    }
    return acc;
}

// Full SpMM (layers 1, 2): one warp per destination row, streaming store.
__global__ void spmm_ell_kernel(const float* __restrict__ uemb,
                                const float* __restrict__ iemb,
                                int stage) {
    int warp = (blockIdx.x * blockDim.x + threadIdx.x) >> 5;
    int lane = threadIdx.x & 31;
    if (warp >= NN) return;
    const float* su; const float* si; float* dst;
    stage_ptrs(stage, uemb, iemb, su, si, dst);
    float2 acc = spmm_row_acc(warp, lane, su, si);
    __stcs(reinterpret_cast<float2*>(dst + (size_t)warp * D + 2 * lane), acc);
}

// Spill mop-up for full layers 0,1 (vector atomics; tiny grid, usually no-op).
__global__ void spill_kernel(const float* __restrict__ uemb,
                             const float* __restrict__ iemb,
                             int stage) {
    int cnt = min(g_spill_count, MAX_SPILL);
    int idx = blockIdx.x * blockDim.x + threadIdx.x;
    int e = idx >> 4;
    int q = idx & 15;
    if (e >= cnt) return;

    const float* su; const float* si; float* dst;
    stage_ptrs(stage, uemb, iemb, su, si, dst);

    int   row = g_srow[e];
    int   col = g_scol[e];
    float v   = g_sval[e];
    const float* srow = (col < NUM_USERS)
                      ? (su + (size_t)col * D)
                      : (si + (size_t)(col - NUM_USERS) * D);
    float4 x = *reinterpret_cast<const float4*>(srow + q * 4);
    float* p = dst + (size_t)row * D + q * 4;
    asm volatile("red.global.add.v4.f32 [%0], {%1, %2, %3, %4};"
                 :: "l"(p), "f"(v * x.x), "f"(v * x.y), "f"(v * x.z), "f"(v * x.w)
                 : "memory");
}

// ---------------------------------------------------------------------------
// Fused layer-3 + dot: one warp per pair; u and i gathers interleaved for ILP.
// gamma[b] = dot( (e0_u+e1_u+e2_u+e3_u)/4 , (e0_i+e1_i+e2_i+e3_i)/4 )
__global__ void final_kernel(const int*   __restrict__ users,
                             const int*   __restrict__ items,
                             const float* __restrict__ uemb,
                             const float* __restrict__ iemb,
                             float*       __restrict__ out) {
    int warp = (blockIdx.x * blockDim.x + threadIdx.x) >> 5;
    int lane = threadIdx.x & 31;
    if (warp >= BATCH) return;

    int u  = __ldg(users + warp);
    int it = __ldg(items + warp);
    int nu = u;
    int ni = NUM_USERS + it;

    const float* bu = g_B;
    const float* bi = g_B + (size_t)NUM_USERS * D;

    // --- fused layer-3 gathers for both endpoints, interleaved ---
    int nru = g_len[nu];
    int nri = g_len[ni];
    int n_u = min(nru, WIDTH);
    int n_i = min(nri, WIDTH);

    int2 evu = make_int2(0, 0), evi = make_int2(0, 0);
    if (lane < n_u) evu = __ldcs(g_ell + (size_t)nu * WIDTH + lane);
    if (lane < n_i) evi = __ldcs(g_ell + (size_t)ni * WIDTH + lane);

    float2 e3u = make_float2(0.f, 0.f);
    float2 e3i = make_float2(0.f, 0.f);
    int nmax = (max(n_u, n_i) + 3) & ~3;
    for (int j = 0; j < nmax; j += 4) {
#pragma unroll
        for (int k = 0; k < 4; k++) {
            int   cu = __shfl_sync(0xFFFFFFFFu, evu.x, j + k);
            float vu = __int_as_float(__shfl_sync(0xFFFFFFFFu, evu.y, j + k));
            int   ci = __shfl_sync(0xFFFFFFFFu, evi.x, j + k);
            float vi = __int_as_float(__shfl_sync(0xFFFFFFFFu, evi.y, j + k));
            if (j + k >= n_u) { cu = 0; vu = 0.f; }
            if (j + k >= n_i) { ci = 0; vi = 0.f; }
            const float* ru = (cu < NUM_USERS)
                            ? (bu + (size_t)cu * D)
                            : (bi + (size_t)(cu - NUM_USERS) * D);
            const float* ri = (ci < NUM_USERS)
                            ? (bu + (size_t)ci * D)
                            : (bi + (size_t)(ci - NUM_USERS) * D);
            float2 xu = *reinterpret_cast<const float2*>(ru + 2 * lane);
            float2 xi = *reinterpret_cast<const float2*>(ri + 2 * lane);
            e3u.x += vu * xu.x;  e3u.y += vu * xu.y;
            e3i.x += vi * xi.x;  e3i.y += vi * xi.y;
        }
    }
    // rare spill patch (only taken for degree > WIDTH endpoints)
    if (nru > WIDTH || nri > WIDTH) {
        int cnt = min(g_spill_count, MAX_SPILL);
        for (int s = 0; s < cnt; s++) {
            int   rs = g_srow[s];
            if (rs != nu && rs != ni) continue;
            int   cj = g_scol[s];
            float vj = g_sval[s];
            const float* sr = (cj < NUM_USERS)
                            ? (bu + (size_t)cj * D)
                            : (bi + (size_t)(cj - NUM_USERS) * D);
            float2 x = *reinterpret_cast<const float2*>(sr + 2 * lane);
            if (rs == nu) { e3u.x += vj * x.x; e3u.y += vj * x.y; }
            if (rs == ni) { e3i.x += vj * x.x; e3i.y += vj * x.y; }
        }
    }

    size_t urow = (size_t)nu * D + 2 * lane;
    size_t irow = (size_t)ni * D + 2 * lane;

    float2 a_u = *reinterpret_cast<const float2*>(g_A + urow);
    float2 b_u = *reinterpret_cast<const float2*>(g_B + urow);
    float2 e0u = *reinterpret_cast<const float2*>(uemb + (size_t)u * D + 2 * lane);
    float2 a_i = *reinterpret_cast<const float2*>(g_A + irow);
    float2 b_i = *reinterpret_cast<const float2*>(g_B + irow);
    float2 e0i = *reinterpret_cast<const float2*>(iemb + (size_t)it * D + 2 * lane);

    float uvx = e0u.x + a_u.x + b_u.x + e3u.x;
    float uvy = e0u.y + a_u.y + b_u.y + e3u.y;
    float ivx = e0i.x + a_i.x + b_i.x + e3i.x;
    float ivy = e0i.y + a_i.y + b_i.y + e3i.y;

    float dot = uvx * ivx + uvy * ivy;
#pragma unroll
    for (int off = 16; off > 0; off >>= 1)
        dot += __shfl_xor_sync(0xFFFFFFFFu, dot, off);

    if (lane == 0) out[warp] = dot * 0.0625f;   // (1/4)*(1/4)
}

// ---------------------------------------------------------------------------
extern "C" void kernel_launch(void* const* d_in, const int* in_sizes, int n_in,
                              void* d_out, int out_size) {
    const int*   users = (const int*)  d_in[0];
    const int*   items = (const int*)  d_in[1];
    const int*   erow  = (const int*)  d_in[2];
    const int*   ecol  = (const int*)  d_in[3];
    const float* evals = (const float*)d_in[4];
    const float* uemb  = (const float*)d_in[5];
    const float* iemb  = (const float*)d_in[6];
    float* out = (float*)d_out;

    // --- build ELL ---
    init_kernel<<<(NN / 4 + 255) / 256, 256>>>();
    ell_fill_kernel<<<(NNZ / 8 + 255) / 256, 256>>>(erow, ecol, evals);

    int threads = 256;                         // 8 warps/block
    int blocks  = (NN + 7) / 8;                // 37500
    int sblocks = (MAX_SPILL * 16) / 256;      // 128

    // --- layers 1,2 full; layer 3 fused into final ---
    spmm_ell_kernel<<<blocks, threads>>>(uemb, iemb, 0);
    spill_kernel<<<sblocks, 256>>>(uemb, iemb, 0);

    spmm_ell_kernel<<<blocks, threads>>>(uemb, iemb, 1);
    spill_kernel<<<sblocks, 256>>>(uemb, iemb, 1);

    // --- fused layer-3 + gather + dot ---
    final_kernel<<<(BATCH + 7) / 8, 256>>>(users, items, uemb, iemb, out);
}

// round 10
// speedup vs baseline: 1.2606x; 1.0538x over previous
#include <cuda_runtime.h>
#include <cuda_bf16.h>

#define NUM_USERS 100000
#define NUM_ITEMS 200000
#define NN        (NUM_USERS + NUM_ITEMS)   // 300000
#define D         64
#define NNZ       5000000
#define BATCH     16384
#define WIDTH     32                         // ELL width (P(deg>32) ~ 5e-5, spill net)
#define MAX_SPILL 2048

// Full layer outputs for layers 1,2 (each 76.8 MB); layer 3 fused into final.
__device__ float g_A[(size_t)NN * D];
__device__ float g_B[(size_t)NN * D];

// ELL storage: packed (col, val_bits). 300000*32*8B = 76.8 MB (L2-resident)
__device__ int2 g_ell[(size_t)NN * WIDTH];
__device__ int  g_len[NN];

// Spill safety net (degree > WIDTH; expected ~tens of edges)
__device__ int   g_spill_count;
__device__ int   g_srow[MAX_SPILL];
__device__ int   g_scol[MAX_SPILL];
__device__ float g_sval[MAX_SPILL];

// ---------------------------------------------------------------------------
__global__ void init_kernel() {
    int i = blockIdx.x * blockDim.x + threadIdx.x;
    const int n4 = NN / 4;                    // 75000
    if (i < n4)
        reinterpret_cast<int4*>(g_len)[i] = make_int4(0, 0, 0, 0);
    if (i == 0) g_spill_count = 0;
}

// 4 edges per thread, vectorized loads (round-7 proven version).
__global__ void ell_fill_kernel(const int*   __restrict__ erow,
                                const int*   __restrict__ ecol,
                                const float* __restrict__ evals) {
    int t = blockIdx.x * blockDim.x + threadIdx.x;
    int i4 = t * 4;
    if (i4 >= NNZ) return;
    int4   r = *reinterpret_cast<const int4*>(erow + i4);
    int4   c = *reinterpret_cast<const int4*>(ecol + i4);
    float4 v = *reinterpret_cast<const float4*>(evals + i4);
    int    rows[4] = {r.x, r.y, r.z, r.w};
    int    cols[4] = {c.x, c.y, c.z, c.w};
    float  vals[4] = {v.x, v.y, v.z, v.w};
#pragma unroll
    for (int k = 0; k < 4; k++) {
        int pos = atomicAdd(&g_len[rows[k]], 1);
        if (pos < WIDTH) {
            g_ell[(size_t)rows[k] * WIDTH + pos] =
                make_int2(cols[k], __float_as_int(vals[k]));
        } else {
            int s = atomicAdd(&g_spill_count, 1);
            if (s < MAX_SPILL) {
                g_srow[s] = rows[k]; g_scol[s] = cols[k]; g_sval[s] = vals[k];
            }
        }
    }
}

// ---------------------------------------------------------------------------
// stage 0: src = (uemb, iemb), dst = g_A ; stage 1: src = g_A, dst = g_B
__device__ __forceinline__ void stage_ptrs(int stage,
                                           const float* uemb, const float* iemb,
                                           const float*& su, const float*& si,
                                           float*& dst) {
    if (stage == 0) { su = uemb; si = iemb;                        dst = g_A; }
    else            { su = g_A;  si = g_A + (size_t)NUM_USERS * D; dst = g_B; }
}

// Warp computes one output row (single ELL chunk, len <= 32). LEAN: no spill
// logic in here. Unroll 8: 8 independent gather loads in flight per warp
// (spmm is L2-latency-bound at MLP=4 — ncu round 8: L2 28.6%, issue 41%).
// Padding iterations carry c=0, v=0: load row 0 (L1-hot), FMA adds 0.
__device__ __forceinline__ float2 spmm_row_acc(int node, int lane,
                                               const float* __restrict__ su,
                                               const float* __restrict__ si) {
    int n = min(g_len[node], WIDTH);
    int2 ev = make_int2(0, 0);
    if (lane < n)
        ev = __ldcs(g_ell + (size_t)node * WIDTH + lane);  // evict-first stream

    float2 acc = make_float2(0.f, 0.f);
    int n8 = (n + 7) & ~7;                    // <= 32
    for (int j = 0; j < n8; j += 8) {
#pragma unroll
        for (int k = 0; k < 8; k++) {
            int   cj = __shfl_sync(0xFFFFFFFFu, ev.x, j + k);
            float vj = __int_as_float(__shfl_sync(0xFFFFFFFFu, ev.y, j + k));
            const float* srow = (cj < NUM_USERS)
                              ? (su + (size_t)cj * D)
                              : (si + (size_t)(cj - NUM_USERS) * D);
            float2 x = *reinterpret_cast<const float2*>(srow + 2 * lane);
            acc.x += vj * x.x;
            acc.y += vj * x.y;
        }
    }
    return acc;
}

// Full SpMM (layers 1, 2): one warp per destination row, streaming store.
__global__ void spmm_ell_kernel(const float* __restrict__ uemb,
                                const float* __restrict__ iemb,
                                int stage) {
    int warp = (blockIdx.x * blockDim.x + threadIdx.x) >> 5;
    int lane = threadIdx.x & 31;
    if (warp >= NN) return;
    const float* su; const float* si; float* dst;
    stage_ptrs(stage, uemb, iemb, su, si, dst);
    float2 acc = spmm_row_acc(warp, lane, su, si);
    __stcs(reinterpret_cast<float2*>(dst + (size_t)warp * D + 2 * lane), acc);
}

// Spill mop-up for full layers 0,1 (vector atomics; tiny grid, usually no-op).
__global__ void spill_kernel(const float* __restrict__ uemb,
                             const float* __restrict__ iemb,
                             int stage) {
    int cnt = min(g_spill_count, MAX_SPILL);
    int idx = blockIdx.x * blockDim.x + threadIdx.x;
    int e = idx >> 4;
    int q = idx & 15;
    if (e >= cnt) return;

    const float* su; const float* si; float* dst;
    stage_ptrs(stage, uemb, iemb, su, si, dst);

    int   row = g_srow[e];
    int   col = g_scol[e];
    float v   = g_sval[e];
    const float* srow = (col < NUM_USERS)
                      ? (su + (size_t)col * D)
                      : (si + (size_t)(col - NUM_USERS) * D);
    float4 x = *reinterpret_cast<const float4*>(srow + q * 4);
    float* p = dst + (size_t)row * D + q * 4;
    asm volatile("red.global.add.v4.f32 [%0], {%1, %2, %3, %4};"
                 :: "l"(p), "f"(v * x.x), "f"(v * x.y), "f"(v * x.z), "f"(v * x.w)
                 : "memory");
}

// ---------------------------------------------------------------------------
// Rare-path: add spill-list contributions for rows with degree > WIDTH.
__device__ __forceinline__ float2 spill_patch(int node, int lane, float2 acc,
                                              const float* __restrict__ su,
                                              const float* __restrict__ si) {
    if (g_len[node] > WIDTH) {                 // ~16 rows in the whole graph
        int cnt = min(g_spill_count, MAX_SPILL);
        for (int s = 0; s < cnt; s++) {
            if (g_srow[s] == node) {
                int   cj = g_scol[s];
                float vj = g_sval[s];
                const float* srow = (cj < NUM_USERS)
                                  ? (su + (size_t)cj * D)
                                  : (si + (size_t)(cj - NUM_USERS) * D);
                float2 x = *reinterpret_cast<const float2*>(srow + 2 * lane);
                acc.x += vj * x.x;
                acc.y += vj * x.y;
            }
        }
    }
    return acc;
}

// Fused layer-3 + dot (round-7 proven version): one warp per pair.
// gamma[b] = dot( (e0_u+e1_u+e2_u+e3_u)/4 , (e0_i+e1_i+e2_i+e3_i)/4 )
__global__ void final_kernel(const int*   __restrict__ users,
                             const int*   __restrict__ items,
                             const float* __restrict__ uemb,
                             const float* __restrict__ iemb,
                             float*       __restrict__ out) {
    int warp = (blockIdx.x * blockDim.x + threadIdx.x) >> 5;
    int lane = threadIdx.x & 31;
    if (warp >= BATCH) return;

    int u  = __ldg(users + warp);
    int it = __ldg(items + warp);
    int nu = u;
    int ni = NUM_USERS + it;

    const float* bu = g_B;
    const float* bi = g_B + (size_t)NUM_USERS * D;

    // e3 at the two endpoints (layer-3 SpMM, inline)
    float2 e3u = spmm_row_acc(nu, lane, bu, bi);
    e3u = spill_patch(nu, lane, e3u, bu, bi);
    float2 e3i = spmm_row_acc(ni, lane, bu, bi);
    e3i = spill_patch(ni, lane, e3i, bu, bi);

    size_t urow = (size_t)nu * D + 2 * lane;
    size_t irow = (size_t)ni * D + 2 * lane;

    float2 a_u = *reinterpret_cast<const float2*>(g_A + urow);
    float2 b_u = *reinterpret_cast<const float2*>(g_B + urow);
    float2 e0u = *reinterpret_cast<const float2*>(uemb + (size_t)u * D + 2 * lane);
    float2 a_i = *reinterpret_cast<const float2*>(g_A + irow);
    float2 b_i = *reinterpret_cast<const float2*>(g_B + irow);
    float2 e0i = *reinterpret_cast<const float2*>(iemb + (size_t)it * D + 2 * lane);

    float uvx = e0u.x + a_u.x + b_u.x + e3u.x;
    float uvy = e0u.y + a_u.y + b_u.y + e3u.y;
    float ivx = e0i.x + a_i.x + b_i.x + e3i.x;
    float ivy = e0i.y + a_i.y + b_i.y + e3i.y;

    float dot = uvx * ivx + uvy * ivy;
#pragma unroll
    for (int off = 16; off > 0; off >>= 1)
        dot += __shfl_xor_sync(0xFFFFFFFFu, dot, off);

    if (lane == 0) out[warp] = dot * 0.0625f;   // (1/4)*(1/4)
}

// ---------------------------------------------------------------------------
extern "C" void kernel_launch(void* const* d_in, const int* in_sizes, int n_in,
                              void* d_out, int out_size) {
    const int*   users = (const int*)  d_in[0];
    const int*   items = (const int*)  d_in[1];
    const int*   erow  = (const int*)  d_in[2];
    const int*   ecol  = (const int*)  d_in[3];
    const float* evals = (const float*)d_in[4];
    const float* uemb  = (const float*)d_in[5];
    const float* iemb  = (const float*)d_in[6];
    float* out = (float*)d_out;

    // --- build ELL ---
    init_kernel<<<(NN / 4 + 255) / 256, 256>>>();
    ell_fill_kernel<<<(NNZ / 4 + 255) / 256, 256>>>(erow, ecol, evals);

    int threads = 256;                         // 8 warps/block
    int blocks  = (NN + 7) / 8;                // 37500
    int sblocks = (MAX_SPILL * 16) / 256;      // 128

    // --- layers 1,2 full; layer 3 fused into final ---
    spmm_ell_kernel<<<blocks, threads>>>(uemb, iemb, 0);
    spill_kernel<<<sblocks, 256>>>(uemb, iemb, 0);

    spmm_ell_kernel<<<blocks, threads>>>(uemb, iemb, 1);
    spill_kernel<<<sblocks, 256>>>(uemb, iemb, 1);

    // --- fused layer-3 + gather + dot ---
    final_kernel<<<(BATCH + 7) / 8, 256>>>(users, items, uemb, iemb, out);
}

// round 12
// speedup vs baseline: 1.5552x; 1.2337x over previous
#include <cuda_runtime.h>
#include <cuda_fp16.h>
#include <cstdint>

#define NUM_USERS 100000
#define NUM_ITEMS 200000
#define NN        (NUM_USERS + NUM_ITEMS)   // 300000
#define D         64
#define UD        (NUM_USERS * D)           // 6400000
#define NNZ       5000000
#define BATCH     16384
#define WIDTH     32                         // ELL width (P(deg>32) ~ 5e-5, spill net)
#define MAX_SPILL 2048

// fp16 embeddings: e0 (converted), layer-1, layer-2 outputs (38.4 MB each)
__device__ __half g_E0[(size_t)NN * D];
__device__ __half g_A[(size_t)NN * D];
__device__ __half g_B[(size_t)NN * D];

// ELL storage: packed (col, val_bits). 300000*32*8B = 76.8 MB (L2-resident)
__device__ int2 g_ell[(size_t)NN * WIDTH];
__device__ int  g_len[NN];

// Spill safety net (degree > WIDTH; expected ~tens of edges)
__device__ int   g_spill_count;
__device__ int   g_srow[MAX_SPILL];
__device__ int   g_scol[MAX_SPILL];
__device__ float g_sval[MAX_SPILL];

// ---------------------------------------------------------------------------
__global__ void init_kernel() {
    int i = blockIdx.x * blockDim.x + threadIdx.x;
    const int n4 = NN / 4;                    // 75000
    if (i < n4)
        reinterpret_cast<int4*>(g_len)[i] = make_int4(0, 0, 0, 0);
    if (i == 0) g_spill_count = 0;
}

// Convert concatenated (uemb, iemb) fp32 -> contiguous fp16 g_E0. 8 elems/thread.
__global__ void convert_kernel(const float* __restrict__ uemb,
                               const float* __restrict__ iemb) {
    long long i8 = ((long long)blockIdx.x * blockDim.x + threadIdx.x) * 8;
    if (i8 >= (long long)NN * D) return;
    const float* src = (i8 < UD) ? (uemb + i8) : (iemb + (i8 - UD));
    float4 a = *reinterpret_cast<const float4*>(src);
    float4 b = *reinterpret_cast<const float4*>(src + 4);
    __half2 h0 = __floats2half2_rn(a.x, a.y);
    __half2 h1 = __floats2half2_rn(a.z, a.w);
    __half2 h2 = __floats2half2_rn(b.x, b.y);
    __half2 h3 = __floats2half2_rn(b.z, b.w);
    uint4 packed = make_uint4(*reinterpret_cast<uint32_t*>(&h0),
                              *reinterpret_cast<uint32_t*>(&h1),
                              *reinterpret_cast<uint32_t*>(&h2),
                              *reinterpret_cast<uint32_t*>(&h3));
    *reinterpret_cast<uint4*>(g_E0 + i8) = packed;
}

// 4 edges per thread, vectorized loads (round-7 proven version).
__global__ void ell_fill_kernel(const int*   __restrict__ erow,
                                const int*   __restrict__ ecol,
                                const float* __restrict__ evals) {
    int t = blockIdx.x * blockDim.x + threadIdx.x;
    int i4 = t * 4;
    if (i4 >= NNZ) return;
    int4   r = *reinterpret_cast<const int4*>(erow + i4);
    int4   c = *reinterpret_cast<const int4*>(ecol + i4);
    float4 v = *reinterpret_cast<const float4*>(evals + i4);
    int    rows[4] = {r.x, r.y, r.z, r.w};
    int    cols[4] = {c.x, c.y, c.z, c.w};
    float  vals[4] = {v.x, v.y, v.z, v.w};
#pragma unroll
    for (int k = 0; k < 4; k++) {
        int pos = atomicAdd(&g_len[rows[k]], 1);
        if (pos < WIDTH) {
            g_ell[(size_t)rows[k] * WIDTH + pos] =
                make_int2(cols[k], __float_as_int(vals[k]));
        } else {
            int s = atomicAdd(&g_spill_count, 1);
            if (s < MAX_SPILL) {
                g_srow[s] = rows[k]; g_scol[s] = cols[k]; g_sval[s] = vals[k];
            }
        }
    }
}

// ---------------------------------------------------------------------------
// Warp computes one output row from fp16 src (contiguous, no user/item split).
// Lane owns dims {2*lane, 2*lane+1}: one 4B half2 gather per edge.
// Padding iterations carry c=0, v=0: load row 0 (L1-hot), FMA adds 0.
__device__ __forceinline__ float2 spmm_row_acc_h(int node, int lane,
                                                 const __half* __restrict__ src) {
    int n = min(g_len[node], WIDTH);
    int2 ev = make_int2(0, 0);
    if (lane < n)
        ev = __ldcs(g_ell + (size_t)node * WIDTH + lane);  // evict-first stream

    float2 acc = make_float2(0.f, 0.f);
    int n8 = (n + 7) & ~7;                    // <= 32
    for (int j = 0; j < n8; j += 8) {
#pragma unroll
        for (int k = 0; k < 8; k++) {
            int   cj = __shfl_sync(0xFFFFFFFFu, ev.x, j + k);
            float vj = __int_as_float(__shfl_sync(0xFFFFFFFFu, ev.y, j + k));
            uint32_t raw = *reinterpret_cast<const uint32_t*>(
                src + (size_t)cj * D + 2 * lane);
            float2 x = __half22float2(*reinterpret_cast<__half2*>(&raw));
            acc.x += vj * x.x;
            acc.y += vj * x.y;
        }
    }
    return acc;
}

// Full SpMM (layers 1, 2): one warp per destination row, streaming fp16 store.
__global__ void spmm_ell_kernel(int stage) {
    int warp = (blockIdx.x * blockDim.x + threadIdx.x) >> 5;
    int lane = threadIdx.x & 31;
    if (warp >= NN) return;

    const __half* src = (stage == 0) ? g_E0 : g_A;
    __half*       dst = (stage == 0) ? g_A  : g_B;

    float2 acc = spmm_row_acc_h(warp, lane, src);
    __half2 h = __floats2half2_rn(acc.x, acc.y);
    uint32_t bits = *reinterpret_cast<uint32_t*>(&h);
    asm volatile("st.global.cs.b32 [%0], %1;"
                 :: "l"(dst + (size_t)warp * D + 2 * lane), "r"(bits) : "memory");
}

// Spill mop-up (tiny grid, usually no-op): 16 threads/edge, 4 dims each,
// two f16x2 reductions per thread.
__global__ void spill_kernel(int stage) {
    int cnt = min(g_spill_count, MAX_SPILL);
    int idx = blockIdx.x * blockDim.x + threadIdx.x;
    int e = idx >> 4;
    int q = idx & 15;
    if (e >= cnt) return;

    const __half* src = (stage == 0) ? g_E0 : g_A;
    __half*       dst = (stage == 0) ? g_A  : g_B;

    int   row = g_srow[e];
    int   col = g_scol[e];
    float v   = g_sval[e];
    const __half* srow = src + (size_t)col * D + q * 4;
    __half* p = dst + (size_t)row * D + q * 4;
#pragma unroll
    for (int h = 0; h < 2; h++) {
        uint32_t raw = *reinterpret_cast<const uint32_t*>(srow + 2 * h);
        float2 x = __half22float2(*reinterpret_cast<__half2*>(&raw));
        __half2 m = __floats2half2_rn(v * x.x, v * x.y);
        uint32_t mb = *reinterpret_cast<uint32_t*>(&m);
        asm volatile("red.global.add.noftz.f16x2 [%0], %1;"
                     :: "l"(p + 2 * h), "r"(mb) : "memory");
    }
}

// ---------------------------------------------------------------------------
// Rare-path: add spill-list contributions for rows with degree > WIDTH.
__device__ __forceinline__ float2 spill_patch_h(int node, int lane, float2 acc,
                                                const __half* __restrict__ src) {
    if (g_len[node] > WIDTH) {                 // ~16 rows in the whole graph
        int cnt = min(g_spill_count, MAX_SPILL);
        for (int s = 0; s < cnt; s++) {
            if (g_srow[s] == node) {
                int   cj = g_scol[s];
                float vj = g_sval[s];
                uint32_t raw = *reinterpret_cast<const uint32_t*>(
                    src + (size_t)cj * D + 2 * lane);
                float2 x = __half22float2(*reinterpret_cast<__half2*>(&raw));
                acc.x += vj * x.x;
                acc.y += vj * x.y;
            }
        }
    }
    return acc;
}

__device__ __forceinline__ float2 load_h2(const __half* p) {
    uint32_t raw = *reinterpret_cast<const uint32_t*>(p);
    return __half22float2(*reinterpret_cast<__half2*>(&raw));
}

// Fused layer-3 + dot: one warp per pair. e3 computed inline from g_B (fp16).
// e0 endpoint terms read exact fp32 inputs.
__global__ void final_kernel(const int*   __restrict__ users,
                             const int*   __restrict__ items,
                             const float* __restrict__ uemb,
                             const float* __restrict__ iemb,
                             float*       __restrict__ out) {
    int warp = (blockIdx.x * blockDim.x + threadIdx.x) >> 5;
    int lane = threadIdx.x & 31;
    if (warp >= BATCH) return;

    int u  = __ldg(users + warp);
    int it = __ldg(items + warp);
    int nu = u;
    int ni = NUM_USERS + it;

    // e3 at the two endpoints (layer-3 SpMM, inline, fp16 gathers)
    float2 e3u = spmm_row_acc_h(nu, lane, g_B);
    e3u = spill_patch_h(nu, lane, e3u, g_B);
    float2 e3i = spmm_row_acc_h(ni, lane, g_B);
    e3i = spill_patch_h(ni, lane, e3i, g_B);

    size_t urow = (size_t)nu * D + 2 * lane;
    size_t irow = (size_t)ni * D + 2 * lane;

    float2 a_u = load_h2(g_A + urow);
    float2 b_u = load_h2(g_B + urow);
    float2 a_i = load_h2(g_A + irow);
    float2 b_i = load_h2(g_B + irow);
    float2 e0u = *reinterpret_cast<const float2*>(uemb + (size_t)u  * D + 2 * lane);
    float2 e0i = *reinterpret_cast<const float2*>(iemb + (size_t)it * D + 2 * lane);

    float uvx = e0u.x + a_u.x + b_u.x + e3u.x;
    float uvy = e0u.y + a_u.y + b_u.y + e3u.y;
    float ivx = e0i.x + a_i.x + b_i.x + e3i.x;
    float ivy = e0i.y + a_i.y + b_i.y + e3i.y;

    float dot = uvx * ivx + uvy * ivy;
#pragma unroll
    for (int off = 16; off > 0; off >>= 1)
        dot += __shfl_xor_sync(0xFFFFFFFFu, dot, off);

    if (lane == 0) out[warp] = dot * 0.0625f;   // (1/4)*(1/4)
}

// ---------------------------------------------------------------------------
extern "C" void kernel_launch(void* const* d_in, const int* in_sizes, int n_in,
                              void* d_out, int out_size) {
    const int*   users = (const int*)  d_in[0];
    const int*   items = (const int*)  d_in[1];
    const int*   erow  = (const int*)  d_in[2];
    const int*   ecol  = (const int*)  d_in[3];
    const float* evals = (const float*)d_in[4];
    const float* uemb  = (const float*)d_in[5];
    const float* iemb  = (const float*)d_in[6];
    float* out = (float*)d_out;

    // --- build ELL + fp16 e0 ---
    init_kernel<<<(NN / 4 + 255) / 256, 256>>>();
    convert_kernel<<<(int)(((long long)NN * D / 8 + 255) / 256), 256>>>(uemb, iemb);
    ell_fill_kernel<<<(NNZ / 4 + 255) / 256, 256>>>(erow, ecol, evals);

    int threads = 256;                         // 8 warps/block
    int blocks  = (NN + 7) / 8;                // 37500
    int sblocks = (MAX_SPILL * 16) / 256;      // 128

    // --- layers 1,2 full; layer 3 fused into final ---
    spmm_ell_kernel<<<blocks, threads>>>(0);
    spill_kernel<<<sblocks, 256>>>(0);

    spmm_ell_kernel<<<blocks, threads>>>(1);
    spill_kernel<<<sblocks, 256>>>(1);

    // --- fused layer-3 + gather + dot ---
    final_kernel<<<(BATCH + 7) / 8, 256>>>(users, items, uemb, iemb, out);
}

// round 13
// speedup vs baseline: 1.7534x; 1.1274x over previous
#include <cuda_runtime.h>
#include <cuda_fp16.h>
#include <cstdint>

#define NUM_USERS 100000
#define NUM_ITEMS 200000
#define NN        (NUM_USERS + NUM_ITEMS)   // 300000
#define D         64
#define UD        (NUM_USERS * D)           // 6400000
#define NNZ       5000000
#define BATCH     16384
#define WIDTH     32                         // ELL width (P(deg>32) ~ 5e-5, spill net)
#define MAX_SPILL 2048
#define FILL_BLOCKS 4883                     // ceil(NNZ/4/256)
#define CONV_BLOCKS 9375                     // NN*D/8/256 exactly

// fp16 embeddings: e0 (converted), layer-1, layer-2 outputs (38.4 MB each)
__device__ __half g_E0[(size_t)NN * D];
__device__ __half g_A[(size_t)NN * D];
__device__ __half g_B[(size_t)NN * D];

// ELL storage: packed (col, val_bits). 300000*32*8B = 76.8 MB (L2-resident)
__device__ int2 g_ell[(size_t)NN * WIDTH];
__device__ int  g_len[NN];

// Spill safety net (degree > WIDTH; expected ~tens of edges)
__device__ int   g_spill_count;
__device__ int   g_srow[MAX_SPILL];
__device__ int   g_scol[MAX_SPILL];
__device__ float g_sval[MAX_SPILL];

// ---------------------------------------------------------------------------
__global__ void init_kernel() {
    int i = blockIdx.x * blockDim.x + threadIdx.x;
    const int n4 = NN / 4;                    // 75000
    if (i < n4)
        reinterpret_cast<int4*>(g_len)[i] = make_int4(0, 0, 0, 0);
    if (i == 0) g_spill_count = 0;
}

// Combined build kernel: blocks [0, FILL_BLOCKS) run ELL fill (atomic-bound),
// blocks [FILL_BLOCKS, +CONV_BLOCKS) run fp32->fp16 convert (DRAM-bound).
// The two phases use disjoint pipes and overlap.
__global__ void build_kernel(const int*   __restrict__ erow,
                             const int*   __restrict__ ecol,
                             const float* __restrict__ evals,
                             const float* __restrict__ uemb,
                             const float* __restrict__ iemb) {
    if (blockIdx.x < FILL_BLOCKS) {
        int t = blockIdx.x * blockDim.x + threadIdx.x;
        int i4 = t * 4;
        if (i4 >= NNZ) return;
        int4   r = *reinterpret_cast<const int4*>(erow + i4);
        int4   c = *reinterpret_cast<const int4*>(ecol + i4);
        float4 v = *reinterpret_cast<const float4*>(evals + i4);
        int    rows[4] = {r.x, r.y, r.z, r.w};
        int    cols[4] = {c.x, c.y, c.z, c.w};
        float  vals[4] = {v.x, v.y, v.z, v.w};
#pragma unroll
        for (int k = 0; k < 4; k++) {
            int pos = atomicAdd(&g_len[rows[k]], 1);
            if (pos < WIDTH) {
                g_ell[(size_t)rows[k] * WIDTH + pos] =
                    make_int2(cols[k], __float_as_int(vals[k]));
            } else {
                int s = atomicAdd(&g_spill_count, 1);
                if (s < MAX_SPILL) {
                    g_srow[s] = rows[k]; g_scol[s] = cols[k]; g_sval[s] = vals[k];
                }
            }
        }
    } else {
        long long i8 = ((long long)(blockIdx.x - FILL_BLOCKS) * blockDim.x
                        + threadIdx.x) * 8;
        if (i8 >= (long long)NN * D) return;
        const float* src = (i8 < UD) ? (uemb + i8) : (iemb + (i8 - UD));
        float4 a = *reinterpret_cast<const float4*>(src);
        float4 b = *reinterpret_cast<const float4*>(src + 4);
        __half2 h0 = __floats2half2_rn(a.x, a.y);
        __half2 h1 = __floats2half2_rn(a.z, a.w);
        __half2 h2 = __floats2half2_rn(b.x, b.y);
        __half2 h3 = __floats2half2_rn(b.z, b.w);
        uint4 packed = make_uint4(*reinterpret_cast<uint32_t*>(&h0),
                                  *reinterpret_cast<uint32_t*>(&h1),
                                  *reinterpret_cast<uint32_t*>(&h2),
                                  *reinterpret_cast<uint32_t*>(&h3));
        *reinterpret_cast<uint4*>(g_E0 + i8) = packed;
    }
}

// ---------------------------------------------------------------------------
// Warp computes one output row. NEW layout: 16 lanes per edge, lane owns dims
// {4*sub .. 4*sub+3} (sub = lane&15); halves (lane>>4) process alternating
// edges; one cross-half shfl reduce at the end. ~5 instr/edge vs ~8.5 before.
// Padding edges carry c=0, v=0: load row 0 (L1-hot), FMA adds 0.
// Returns float4 (reduced, identical in lane and lane^16).
__device__ __forceinline__ float4 spmm_row_acc_h(int node, int lane,
                                                 const __half* __restrict__ src) {
    int n = min(g_len[node], WIDTH);
    int sub  = lane & 15;
    int half_id = lane >> 4;

    int2 ev = make_int2(0, 0);
    if (lane < n)
        ev = __ldcs(g_ell + (size_t)node * WIDTH + lane);  // evict-first stream

    float4 acc = make_float4(0.f, 0.f, 0.f, 0.f);
    int n8 = (n + 7) & ~7;                    // <= 32
    for (int j = 0; j < n8; j += 8) {
#pragma unroll
        for (int k = 0; k < 4; k++) {
            int idx = j + 2 * k + half_id;    // this half's edge
            int   cj = __shfl_sync(0xFFFFFFFFu, ev.x, idx);
            float vj = __int_as_float(__shfl_sync(0xFFFFFFFFu, ev.y, idx));
            uint2 raw = *reinterpret_cast<const uint2*>(
                src + (size_t)cj * D + 4 * sub);
            float2 x0 = __half22float2(*reinterpret_cast<__half2*>(&raw.x));
            float2 x1 = __half22float2(*reinterpret_cast<__half2*>(&raw.y));
            acc.x += vj * x0.x;
            acc.y += vj * x0.y;
            acc.z += vj * x1.x;
            acc.w += vj * x1.y;
        }
    }
    // cross-half reduce: lanes L and L^16 hold partials for the same dims
    acc.x += __shfl_xor_sync(0xFFFFFFFFu, acc.x, 16);
    acc.y += __shfl_xor_sync(0xFFFFFFFFu, acc.y, 16);
    acc.z += __shfl_xor_sync(0xFFFFFFFFu, acc.z, 16);
    acc.w += __shfl_xor_sync(0xFFFFFFFFu, acc.w, 16);
    return acc;
}

// Rare-path (post-reduce): add spill contributions for rows deg > WIDTH.
// Each lane updates its own copy; downstream readers use lanes < 16.
__device__ __forceinline__ float4 spill_patch_h(int node, int lane, float4 acc,
                                                const __half* __restrict__ src) {
    if (g_len[node] > WIDTH) {                 // ~16 rows in the whole graph
        int sub = lane & 15;
        int cnt = min(g_spill_count, MAX_SPILL);
        for (int s = 0; s < cnt; s++) {
            if (g_srow[s] == node) {
                int   cj = g_scol[s];
                float vj = g_sval[s];
                uint2 raw = *reinterpret_cast<const uint2*>(
                    src + (size_t)cj * D + 4 * sub);
                float2 x0 = __half22float2(*reinterpret_cast<__half2*>(&raw.x));
                float2 x1 = __half22float2(*reinterpret_cast<__half2*>(&raw.y));
                acc.x += vj * x0.x;
                acc.y += vj * x0.y;
                acc.z += vj * x1.x;
                acc.w += vj * x1.y;
            }
        }
    }
    return acc;
}

// Full SpMM (layers 1, 2): one warp per destination row; lanes<16 store 8B each.
__global__ void spmm_ell_kernel(int stage) {
    int warp = (blockIdx.x * blockDim.x + threadIdx.x) >> 5;
    int lane = threadIdx.x & 31;
    if (warp >= NN) return;

    const __half* src = (stage == 0) ? g_E0 : g_A;
    __half*       dst = (stage == 0) ? g_A  : g_B;

    float4 acc = spmm_row_acc_h(warp, lane, src);

    if (lane < 16) {
        __half2 h0 = __floats2half2_rn(acc.x, acc.y);
        __half2 h1 = __floats2half2_rn(acc.z, acc.w);
        uint32_t b0 = *reinterpret_cast<uint32_t*>(&h0);
        uint32_t b1 = *reinterpret_cast<uint32_t*>(&h1);
        asm volatile("st.global.cs.v2.b32 [%0], {%1, %2};"
                     :: "l"(dst + (size_t)warp * D + 4 * lane), "r"(b0), "r"(b1)
                     : "memory");
    }
}

// Spill mop-up (tiny grid, usually no-op): 16 threads/edge, 4 dims each.
__global__ void spill_kernel(int stage) {
    int cnt = min(g_spill_count, MAX_SPILL);
    int idx = blockIdx.x * blockDim.x + threadIdx.x;
    int e = idx >> 4;
    int q = idx & 15;
    if (e >= cnt) return;

    const __half* src = (stage == 0) ? g_E0 : g_A;
    __half*       dst = (stage == 0) ? g_A  : g_B;

    int   row = g_srow[e];
    int   col = g_scol[e];
    float v   = g_sval[e];
    const __half* srow = src + (size_t)col * D + q * 4;
    __half* p = dst + (size_t)row * D + q * 4;
#pragma unroll
    for (int h = 0; h < 2; h++) {
        uint32_t raw = *reinterpret_cast<const uint32_t*>(srow + 2 * h);
        float2 x = __half22float2(*reinterpret_cast<__half2*>(&raw));
        __half2 m = __floats2half2_rn(v * x.x, v * x.y);
        uint32_t mb = *reinterpret_cast<uint32_t*>(&m);
        asm volatile("red.global.add.noftz.f16x2 [%0], %1;"
                     :: "l"(p + 2 * h), "r"(mb) : "memory");
    }
}

// ---------------------------------------------------------------------------
// Fused layer-3 + dot: one warp per pair. e3 computed inline from g_B (fp16).
// e0 endpoint terms read exact fp32 inputs. Lanes<16 own 4 dims each.
__global__ void final_kernel(const int*   __restrict__ users,
                             const int*   __restrict__ items,
                             const float* __restrict__ uemb,
                             const float* __restrict__ iemb,
                             float*       __restrict__ out) {
    int warp = (blockIdx.x * blockDim.x + threadIdx.x) >> 5;
    int lane = threadIdx.x & 31;
    if (warp >= BATCH) return;

    int u  = __ldg(users + warp);
    int it = __ldg(items + warp);
    int nu = u;
    int ni = NUM_USERS + it;

    // e3 at the two endpoints (layer-3 SpMM, inline, fp16 gathers)
    float4 e3u = spmm_row_acc_h(nu, lane, g_B);
    e3u = spill_patch_h(nu, lane, e3u, g_B);
    float4 e3i = spmm_row_acc_h(ni, lane, g_B);
    e3i = spill_patch_h(ni, lane, e3i, g_B);

    float dot = 0.f;
    if (lane < 16) {
        int sub = lane;
        size_t urow = (size_t)nu * D + 4 * sub;
        size_t irow = (size_t)ni * D + 4 * sub;

        uint2 rauh = *reinterpret_cast<const uint2*>(g_A + urow);
        uint2 rbuh = *reinterpret_cast<const uint2*>(g_B + urow);
        uint2 raih = *reinterpret_cast<const uint2*>(g_A + irow);
        uint2 rbih = *reinterpret_cast<const uint2*>(g_B + irow);
        float4 e0u = *reinterpret_cast<const float4*>(uemb + (size_t)u  * D + 4 * sub);
        float4 e0i = *reinterpret_cast<const float4*>(iemb + (size_t)it * D + 4 * sub);

        float2 au0 = __half22float2(*reinterpret_cast<__half2*>(&rauh.x));
        float2 au1 = __half22float2(*reinterpret_cast<__half2*>(&rauh.y));
        float2 bu0 = __half22float2(*reinterpret_cast<__half2*>(&rbuh.x));
        float2 bu1 = __half22float2(*reinterpret_cast<__half2*>(&rbuh.y));
        float2 ai0 = __half22float2(*reinterpret_cast<__half2*>(&raih.x));
        float2 ai1 = __half22float2(*reinterpret_cast<__half2*>(&raih.y));
        float2 bi0 = __half22float2(*reinterpret_cast<__half2*>(&rbih.x));
        float2 bi1 = __half22float2(*reinterpret_cast<__half2*>(&rbih.y));

        float uv0 = e0u.x + au0.x + bu0.x + e3u.x;
        float uv1 = e0u.y + au0.y + bu0.y + e3u.y;
        float uv2 = e0u.z + au1.x + bu1.x + e3u.z;
        float uv3 = e0u.w + au1.y + bu1.y + e3u.w;
        float iv0 = e0i.x + ai0.x + bi0.x + e3i.x;
        float iv1 = e0i.y + ai0.y + bi0.y + e3i.y;
        float iv2 = e0i.z + ai1.x + bi1.x + e3i.z;
        float iv3 = e0i.w + ai1.y + bi1.y + e3i.w;

        dot = uv0 * iv0 + uv1 * iv1 + uv2 * iv2 + uv3 * iv3;
    }
#pragma unroll
    for (int off = 16; off > 0; off >>= 1)
        dot += __shfl_xor_sync(0xFFFFFFFFu, dot, off);

    if (lane == 0) out[warp] = dot * 0.0625f;   // (1/4)*(1/4)
}

// ---------------------------------------------------------------------------
extern "C" void kernel_launch(void* const* d_in, const int* in_sizes, int n_in,
                              void* d_out, int out_size) {
    const int*   users = (const int*)  d_in[0];
    const int*   items = (const int*)  d_in[1];
    const int*   erow  = (const int*)  d_in[2];
    const int*   ecol  = (const int*)  d_in[3];
    const float* evals = (const float*)d_in[4];
    const float* uemb  = (const float*)d_in[5];
    const float* iemb  = (const float*)d_in[6];
    float* out = (float*)d_out;

    // --- init, then overlapped ELL fill + fp16 convert ---
    init_kernel<<<(NN / 4 + 255) / 256, 256>>>();
    build_kernel<<<FILL_BLOCKS + CONV_BLOCKS, 256>>>(erow, ecol, evals, uemb, iemb);

    int threads = 256;                         // 8 warps/block
    int blocks  = (NN + 7) / 8;                // 37500
    int sblocks = (MAX_SPILL * 16) / 256;      // 128

    // --- layers 1,2 full; layer 3 fused into final ---
    spmm_ell_kernel<<<blocks, threads>>>(0);
    spill_kernel<<<sblocks, 256>>>(0);

    spmm_ell_kernel<<<blocks, threads>>>(1);
    spill_kernel<<<sblocks, 256>>>(1);

    // --- fused layer-3 + gather + dot ---
    final_kernel<<<(BATCH + 7) / 8, 256>>>(users, items, uemb, iemb, out);
}